// round 16
// baseline (speedup 1.0000x reference)
#include <cuda_runtime.h>
#include <cuda_fp16.h>
#include <stdint.h>
#include <math.h>

#define NHEADS 12
#define DH     64
#define LW     49
#define CCH    768
#define NWIN   2048
#define MROWS  (NWIN * LW)                 // 100352

// ---------------- device-global fp16 planes --------------------------------
__device__ __half g_sh[(size_t)MROWS * CCH];          // attention out
__device__ __half g_wqh[12 * 4096], g_wkh[12 * 4096], g_wvh[12 * 4096];
__device__ __half g_woh[589824];

// ---------------- helpers ---------------------------------------------------
__device__ __forceinline__ void mma_f16(float c[4], const uint32_t a[4],
                                        uint32_t b0, uint32_t b1) {
    asm volatile(
        "mma.sync.aligned.m16n8k16.row.col.f32.f16.f16.f32 "
        "{%0,%1,%2,%3},{%4,%5,%6,%7},{%8,%9},{%0,%1,%2,%3};\n"
        : "+f"(c[0]), "+f"(c[1]), "+f"(c[2]), "+f"(c[3])
        : "r"(a[0]), "r"(a[1]), "r"(a[2]), "r"(a[3]), "r"(b0), "r"(b1));
}

__device__ __forceinline__ void ldsm4(uint32_t r[4], uint32_t saddr) {
    asm volatile("ldmatrix.sync.aligned.m8n8.x4.shared.b16 {%0,%1,%2,%3},[%4];"
                 : "=r"(r[0]), "=r"(r[1]), "=r"(r[2]), "=r"(r[3]) : "r"(saddr));
}

__device__ __forceinline__ void ldsm4t(uint32_t r[4], uint32_t saddr) {
    asm volatile("ldmatrix.sync.aligned.m8n8.x4.trans.shared.b16 {%0,%1,%2,%3},[%4];"
                 : "=r"(r[0]), "=r"(r[1]), "=r"(r[2]), "=r"(r[3]) : "r"(saddr));
}

__device__ __forceinline__ uint32_t packh(__half a, __half b) {
    __half2 t; t.x = a; t.y = b;
    return *reinterpret_cast<uint32_t*>(&t);
}

__device__ __forceinline__ void cpa16(uint32_t dst, const void* src) {
    asm volatile("cp.async.cg.shared.global [%0], [%1], 16;" :: "r"(dst), "l"(src));
}
__device__ __forceinline__ void cpa_commit() { asm volatile("cp.async.commit_group;"); }
template<int N> __device__ __forceinline__ void cpa_wait() {
    asm volatile("cp.async.wait_group %0;" :: "n"(N));
}

// SW128-swizzled byte offset within a plane of 128-B rows.
__device__ __forceinline__ uint32_t swo(int row, uint32_t col) {
    return ((uint32_t)row << 7) + (col ^ (((uint32_t)row & 7u) << 4));
}

// ============================================================================
// Prep: weights, all hi-only fp16.
// ============================================================================
__global__ void split_w_kernel(const float* __restrict__ Wq, const float* __restrict__ Wk,
                               const float* __restrict__ Wv, const float* __restrict__ Wo) {
    int np = 589824 / 2;
    for (int i = blockIdx.x * blockDim.x + threadIdx.x; i < np;
         i += gridDim.x * blockDim.x) {
        float2 v = ((const float2*)Wo)[i];
        ((uint32_t*)g_woh)[i] = packh(__float2half(v.x), __float2half(v.y));
        if (i < 24576) {
            float2 q = ((const float2*)Wq)[i];
            ((uint32_t*)g_wqh)[i] = packh(__float2half(q.x), __float2half(q.y));
            float2 k = ((const float2*)Wk)[i];
            ((uint32_t*)g_wkh)[i] = packh(__float2half(k.x), __float2half(k.y));
            float2 w = ((const float2*)Wv)[i];
            ((uint32_t*)g_wvh)[i] = packh(__float2half(w.x), __float2half(w.y));
        }
    }
}

// ============================================================================
// Kernel A: fused QKV projection + attention, fp16, SW128 unpadded planes.
// Planes (8192 B): 0=x 1=Wq 2=Wk->V 3=Q->P 4=K 5=Wv. Sc aliases planes 0-1.
// Phases: stage (x LDGs first) | QK (cache x frags) | scores+V | softmax | PV.
// (identical to round 14 — best known attn)
// ============================================================================
#define PLB   8192
#define SMEMB (6 * PLB)                // 49152 B -> 4 CTAs/SM
#define SCST  65

__device__ __forceinline__ void gemm_pass(float acc[2][4][4], uint32_t aBase,
                                          uint32_t bBase, int mbase, int nbase,
                                          int lane) {
    const int r16 = lane & 15;
    const uint32_t kaq = (lane >> 4) * 16;
    #pragma unroll
    for (int kc = 0; kc < 4; ++kc) {
        uint32_t ka = kaq + kc * 32;
        uint32_t a0[4], a1[4], b0[4], b1[4];
        uint32_t a0a = aBase + swo(mbase + r16, ka);
        uint32_t b0a = bBase + swo(nbase + r16, ka);
        ldsm4(a0, a0a);
        ldsm4(a1, a0a + 2048);
        ldsm4(b0, b0a);
        ldsm4(b1, b0a + 2048);
        mma_f16(acc[0][0], a0, b0[0], b0[2]);
        mma_f16(acc[0][1], a0, b0[1], b0[3]);
        mma_f16(acc[0][2], a0, b1[0], b1[2]);
        mma_f16(acc[0][3], a0, b1[1], b1[3]);
        mma_f16(acc[1][0], a1, b0[0], b0[2]);
        mma_f16(acc[1][1], a1, b0[1], b0[3]);
        mma_f16(acc[1][2], a1, b1[0], b1[2]);
        mma_f16(acc[1][3], a1, b1[1], b1[3]);
    }
}

// A row-major, B row-major [k][n] via ldmatrix.trans (for P @ V)
__device__ __forceinline__ void gemm_pass_tb(float acc[2][4][4], uint32_t aBase,
                                             uint32_t bBase, int mbase, int nbase,
                                             int lane) {
    const int r16 = lane & 15;
    const uint32_t kaq = (lane >> 4) * 16;
    const int krow = ((lane >> 4) << 3) + (lane & 7);
    const int nch = ((lane >> 3) & 1) * 8;
    #pragma unroll
    for (int kc = 0; kc < 4; ++kc) {
        uint32_t ka = kaq + kc * 32;
        uint32_t a0[4], a1[4], b0[4], b1[4];
        uint32_t a0a = aBase + swo(mbase + r16, ka);
        ldsm4(a0, a0a);
        ldsm4(a1, a0a + 2048);
        const int rowB = kc * 16 + krow;
        ldsm4t(b0, bBase + swo(rowB, (nbase + nch) * 2));
        ldsm4t(b1, bBase + swo(rowB, (nbase + 16 + nch) * 2));
        mma_f16(acc[0][0], a0, b0[0], b0[2]);
        mma_f16(acc[0][1], a0, b0[1], b0[3]);
        mma_f16(acc[0][2], a0, b1[0], b1[2]);
        mma_f16(acc[0][3], a0, b1[1], b1[3]);
        mma_f16(acc[1][0], a1, b0[0], b0[2]);
        mma_f16(acc[1][1], a1, b0[1], b0[3]);
        mma_f16(acc[1][2], a1, b1[0], b1[2]);
        mma_f16(acc[1][3], a1, b1[1], b1[3]);
    }
}

__global__ void __launch_bounds__(128, 4)
attn_kernel(const float* __restrict__ x)
{
    extern __shared__ char smc[];
    float* Sc = (float*)smc;               // fp32 scores, aliases planes 0-1

    const int tid = threadIdx.x, lane = tid & 31, wid = tid >> 5;
    const int warp_m = wid >> 1, warp_n = wid & 1;
    const int mbase = warp_m * 32, nbase = warp_n * 32;
    const int lr = lane >> 2, lc = lane & 3;

    const int h = blockIdx.x % NHEADS;
    const int n = blockIdx.x / NHEADS;
    const int b = n >> 6, hb = (n >> 3) & 7, wb = n & 7;

    const uint32_t sb = (uint32_t)__cvta_generic_to_shared(smc);
    const uint32_t sX = sb, sWQ = sb + PLB, sWK = sb + 2 * PLB;
    const uint32_t sV = sb + 2 * PLB;      // V overwrites Wk
    const uint32_t sQ = sb + 3 * PLB;      // Q, later P
    const uint32_t sK = sb + 4 * PLB;
    const uint32_t sWV = sb + 5 * PLB;

    // ---- issue x fp32 LDGs FIRST (latency overlaps cp.async issue below) ----
    float4 xf0[4], xf1[4];
    int xl[4], xch[4];
    #pragma unroll
    for (int it = 0; it < 4; ++it) {
        int q = tid + it * 128;
        int l = q >> 3, ch = q & 7;
        xl[it] = l; xch[it] = ch;
        xf0[it] = make_float4(0.f, 0.f, 0.f, 0.f);
        xf1[it] = make_float4(0.f, 0.f, 0.f, 0.f);
        if (l < LW) {
            int i = l / 7, j = l - i * 7;
            const float* src = x + (((size_t)(b * 56 + hb * 7 + i)) * 56 + (wb * 7 + j)) * CCH
                               + h * DH + ch * 8;
            xf0[it] = *(const float4*)src;
            xf1[it] = *(const float4*)(src + 4);
        }
    }

    // ---- cp.async weights (Wq->1, Wk->2, Wv->5), swizzled ----
    for (int q = tid; q < 1536; q += 128) {
        int pl = q >> 9;
        int rem = q & 511, e = rem >> 3, ch = rem & 7;
        const __half* src = (pl == 0 ? g_wqh : pl == 1 ? g_wkh : g_wvh)
                            + h * 4096 + e * 64 + ch * 8;
        uint32_t plane = (pl == 0) ? 1u : (pl == 1) ? 2u : 5u;
        cpa16(sb + plane * PLB + swo(e, ch * 16), src);
    }
    cpa_commit();

    // ---- convert + store x (LDGs have had time to land) ----
    #pragma unroll
    for (int it = 0; it < 4; ++it) {
        uint4 hv;
        hv.x = packh(__float2half(xf0[it].x), __float2half(xf0[it].y));
        hv.y = packh(__float2half(xf0[it].z), __float2half(xf0[it].w));
        hv.z = packh(__float2half(xf1[it].x), __float2half(xf1[it].y));
        hv.w = packh(__float2half(xf1[it].z), __float2half(xf1[it].w));
        *(uint4*)(smc + swo(xl[it], xch[it] * 16)) = hv;
    }
    cpa_wait<0>();
    __syncthreads();                        // barrier 1

    // ---- merged Q & K projections; CACHE x A-fragments in registers ----
    uint32_t axc[4][2][4];
    {
        float aq[2][4][4] = {}, ak[2][4][4] = {};
        const int r16 = lane & 15;
        const uint32_t kaq = (lane >> 4) * 16;
        #pragma unroll
        for (int kc = 0; kc < 4; ++kc) {
            uint32_t ka = kaq + kc * 32;
            uint32_t bq0[4], bq1[4], bk0[4], bk1[4];
            uint32_t a0a = sX + swo(mbase + r16, ka);
            uint32_t q0a = sWQ + swo(nbase + r16, ka);
            uint32_t k0a = sWK + swo(nbase + r16, ka);
            ldsm4(axc[kc][0], a0a); ldsm4(axc[kc][1], a0a + 2048);
            ldsm4(bq0, q0a); ldsm4(bq1, q0a + 2048);
            ldsm4(bk0, k0a); ldsm4(bk1, k0a + 2048);
            mma_f16(aq[0][0], axc[kc][0], bq0[0], bq0[2]);
            mma_f16(aq[0][1], axc[kc][0], bq0[1], bq0[3]);
            mma_f16(aq[0][2], axc[kc][0], bq1[0], bq1[2]);
            mma_f16(aq[0][3], axc[kc][0], bq1[1], bq1[3]);
            mma_f16(aq[1][0], axc[kc][1], bq0[0], bq0[2]);
            mma_f16(aq[1][1], axc[kc][1], bq0[1], bq0[3]);
            mma_f16(aq[1][2], axc[kc][1], bq1[0], bq1[2]);
            mma_f16(aq[1][3], axc[kc][1], bq1[1], bq1[3]);
            mma_f16(ak[0][0], axc[kc][0], bk0[0], bk0[2]);
            mma_f16(ak[0][1], axc[kc][0], bk0[1], bk0[3]);
            mma_f16(ak[0][2], axc[kc][0], bk1[0], bk1[2]);
            mma_f16(ak[0][3], axc[kc][0], bk1[1], bk1[3]);
            mma_f16(ak[1][0], axc[kc][1], bk0[0], bk0[2]);
            mma_f16(ak[1][1], axc[kc][1], bk0[1], bk0[3]);
            mma_f16(ak[1][2], axc[kc][1], bk1[0], bk1[2]);
            mma_f16(ak[1][3], axc[kc][1], bk1[1], bk1[3]);
        }
        #pragma unroll
        for (int f = 0; f < 2; ++f)
            #pragma unroll
            for (int g = 0; g < 4; ++g) {
                int r = mbase + 16 * f + lr;
                uint32_t off = swo(r, (uint32_t)(nbase + 8 * g + 2 * lc) * 2);
                *(uint32_t*)(smc + 3 * PLB + off) =
                    packh(__float2half(aq[f][g][0]), __float2half(aq[f][g][1]));
                *(uint32_t*)(smc + 3 * PLB + off + 1024) =
                    packh(__float2half(aq[f][g][2]), __float2half(aq[f][g][3]));
                *(uint32_t*)(smc + 4 * PLB + off) =
                    packh(__float2half(ak[f][g][0]), __float2half(ak[f][g][1]));
                *(uint32_t*)(smc + 4 * PLB + off + 1024) =
                    packh(__float2half(ak[f][g][2]), __float2half(ak[f][g][3]));
            }
    }
    __syncthreads();                        // barrier 2 (Wq/Wk dead, x via regs)

    // ---- MERGED phase: scores (Q@K^T -> Sc over x planes) + V (cached x) ----
    {
        // scores; warp_n==1 skips g==3 (cols 56-63, all masked by softmax)
        float acc[2][4][4] = {};
        const int r16 = lane & 15;
        const uint32_t kaq = (lane >> 4) * 16;
        const int gmax = (warp_n == 0) ? 4 : 3;
        #pragma unroll
        for (int kc = 0; kc < 4; ++kc) {
            uint32_t ka = kaq + kc * 32;
            uint32_t a0[4], a1[4], b0[4], b1[4];
            uint32_t a0a = sQ + swo(mbase + r16, ka);
            uint32_t b0a = sK + swo(nbase + r16, ka);
            ldsm4(a0, a0a); ldsm4(a1, a0a + 2048);
            ldsm4(b0, b0a); ldsm4(b1, b0a + 2048);
            mma_f16(acc[0][0], a0, b0[0], b0[2]);
            mma_f16(acc[0][1], a0, b0[1], b0[3]);
            mma_f16(acc[0][2], a0, b1[0], b1[2]);
            mma_f16(acc[1][0], a1, b0[0], b0[2]);
            mma_f16(acc[1][1], a1, b0[1], b0[3]);
            mma_f16(acc[1][2], a1, b1[0], b1[2]);
            if (gmax == 4) {
                mma_f16(acc[0][3], a0, b1[1], b1[3]);
                mma_f16(acc[1][3], a1, b1[1], b1[3]);
            }
        }
        #pragma unroll
        for (int f = 0; f < 2; ++f)
            for (int g = 0; g < 4; ++g) {
                if (g >= gmax) break;
                int r = mbase + 16 * f + lr;
                int c = nbase + 8 * g + 2 * lc;
                if (r < LW) {
                    Sc[r * SCST + c]     = acc[f][g][0] * 0.125f;
                    Sc[r * SCST + c + 1] = acc[f][g][1] * 0.125f;
                }
                if (r + 8 < LW) {
                    Sc[(r + 8) * SCST + c]     = acc[f][g][2] * 0.125f;
                    Sc[(r + 8) * SCST + c + 1] = acc[f][g][3] * 0.125f;
                }
            }
    }
    {
        // V = x @ Wv using cached A-fragments (no x plane reads)
        float acc[2][4][4] = {};
        const int r16 = lane & 15;
        const uint32_t kaq = (lane >> 4) * 16;
        #pragma unroll
        for (int kc = 0; kc < 4; ++kc) {
            uint32_t ka = kaq + kc * 32;
            uint32_t b0[4], b1[4];
            uint32_t b0a = sWV + swo(nbase + r16, ka);
            ldsm4(b0, b0a);
            ldsm4(b1, b0a + 2048);
            mma_f16(acc[0][0], axc[kc][0], b0[0], b0[2]);
            mma_f16(acc[0][1], axc[kc][0], b0[1], b0[3]);
            mma_f16(acc[0][2], axc[kc][0], b1[0], b1[2]);
            mma_f16(acc[0][3], axc[kc][0], b1[1], b1[3]);
            mma_f16(acc[1][0], axc[kc][1], b0[0], b0[2]);
            mma_f16(acc[1][1], axc[kc][1], b0[1], b0[3]);
            mma_f16(acc[1][2], axc[kc][1], b1[0], b1[2]);
            mma_f16(acc[1][3], axc[kc][1], b1[1], b1[3]);
        }
        #pragma unroll
        for (int f = 0; f < 2; ++f)
            #pragma unroll
            for (int g = 0; g < 4; ++g) {
                int r = mbase + 16 * f + lr;
                uint32_t off = swo(r, (uint32_t)(nbase + 8 * g + 2 * lc) * 2);
                *(uint32_t*)(smc + 2 * PLB + off) =
                    packh(__float2half(acc[f][g][0]), __float2half(acc[f][g][1]));
                *(uint32_t*)(smc + 2 * PLB + off + 1024) =
                    packh(__float2half(acc[f][g][2]), __float2half(acc[f][g][3]));
            }
    }
    __syncthreads();                        // barrier 3

    // ---- softmax: 2 threads per row, write P into plane 3 (over Q) ----
    if (tid < 2 * LW) {
        const int r = tid >> 1, half = tid & 1;
        const unsigned msk = (tid < 96) ? 0xFFFFFFFFu : 0x3u;
        float* row = Sc + r * SCST;
        const int m0 = half ? 25 : 0, m1 = half ? LW : 25;
        float mx = -1e30f;
        #pragma unroll
        for (int m = m0; m < m1; ++m) mx = fmaxf(mx, row[m]);
        mx = fmaxf(mx, __shfl_xor_sync(msk, mx, 1));
        float s = 0.f;
        #pragma unroll
        for (int m = m0; m < m1; ++m) { float e = __expf(row[m] - mx); row[m] = e; s += e; }
        s += __shfl_xor_sync(msk, s, 1);
        float inv = 1.f / s;
        __syncwarp(msk);
        #pragma unroll
        for (int mw = half * 16; mw < half * 16 + 16; ++mw) {
            int mc = 2 * mw;
            float p0 = (mc     < LW) ? row[mc] * inv     : 0.f;
            float p1 = (mc + 1 < LW) ? row[mc + 1] * inv : 0.f;
            *(uint32_t*)(smc + 3 * PLB + swo(r, (uint32_t)mw * 4)) =
                packh(__float2half(p0), __float2half(p1));
        }
    }
    __syncthreads();                        // barrier 4

    // ---- out = P @ V (trans-B ldsm), store fp16 to g_sh ----
    {
        float acc[2][4][4] = {};
        gemm_pass_tb(acc, sQ, sV, mbase, nbase, lane);
        #pragma unroll
        for (int f = 0; f < 2; ++f)
            #pragma unroll
            for (int g = 0; g < 4; ++g) {
                int r = mbase + 16 * f + lr;
                int c = nbase + 8 * g + 2 * lc;
                if (r < LW) {
                    size_t off = ((size_t)n * LW + r) * CCH + h * DH + c;
                    *(uint32_t*)(g_sh + off) =
                        packh(__float2half(acc[f][g][0]), __float2half(acc[f][g][1]));
                }
                if (r + 8 < LW) {
                    size_t off = ((size_t)n * LW + r + 8) * CCH + h * DH + c;
                    *(uint32_t*)(g_sh + off) =
                        packh(__float2half(acc[f][g][2]), __float2half(acc[f][g][3]));
                }
            }
    }
}

// ============================================================================
// Kernel B: y = S @ Wo^T + bo, pure fp16 GEMM. CTA tile 128x128, warp 32x64,
// BK=64, SW128 rows, 2-stage double buffer, 256 threads, 3 CTAs/SM.
// ============================================================================
#define PSTG 32768
#define QA   0
#define QB   16384
#define PROJ_SMEM (2 * PSTG)           // 65536 B -> 3 CTAs/SM

__device__ __forceinline__ void proj_stage(uint32_t sb, int s, int kt,
                                           int m_base, int n_base, int tid) {
    const uint32_t base = sb + s * PSTG;
    #pragma unroll
    for (int c = tid; c < 1024; c += 256) {
        int row = c >> 3, ch = c & 7;
        cpa16(base + QA + swo(row, ch * 16),
              g_sh + (size_t)(m_base + row) * CCH + kt + ch * 8);
    }
    #pragma unroll
    for (int c = tid; c < 1024; c += 256) {
        int row = c >> 3, ch = c & 7;
        cpa16(base + QB + swo(row, ch * 16),
              g_woh + (size_t)(n_base + row) * CCH + kt + ch * 8);
    }
    cpa_commit();
}

__global__ void __launch_bounds__(256, 3)
proj_kernel(const float* __restrict__ bo, float* __restrict__ y)
{
    extern __shared__ char psm[];
    const int tid = threadIdx.x, lane = tid & 31, wid = tid >> 5;
    const int warp_m = wid >> 1, warp_n = wid & 1;
    const int lr = lane >> 2, lc = lane & 3;
    const int n_base = (blockIdx.x % 6) * 128;
    const int m_base = (blockIdx.x / 6) * 128;
    const uint32_t sb = (uint32_t)__cvta_generic_to_shared(psm);
    const int r16 = lane & 15;
    const uint32_t kaq = (lane >> 4) * 16;

    float acc[2][8][4] = {};

    auto compute = [&](int s) {
        const uint32_t aB = sb + s * PSTG + QA;
        const uint32_t bB = sb + s * PSTG + QB;
        #pragma unroll
        for (int kc = 0; kc < 4; ++kc) {
            uint32_t ka = kaq + kc * 32;
            uint32_t a0[4], a1[4], bf[4][4];
            uint32_t a0a = aB + swo(warp_m * 32 + r16, ka);
            ldsm4(a0, a0a);
            ldsm4(a1, a0a + 2048);
            #pragma unroll
            for (int nn = 0; nn < 4; ++nn)
                ldsm4(bf[nn], bB + swo(warp_n * 64 + nn * 16 + r16, ka));
            #pragma unroll
            for (int nn = 0; nn < 4; ++nn) {
                mma_f16(acc[0][2 * nn],     a0, bf[nn][0], bf[nn][2]);
                mma_f16(acc[0][2 * nn + 1], a0, bf[nn][1], bf[nn][3]);
                mma_f16(acc[1][2 * nn],     a1, bf[nn][0], bf[nn][2]);
                mma_f16(acc[1][2 * nn + 1], a1, bf[nn][1], bf[nn][3]);
            }
        }
    };

    proj_stage(sb, 0, 0, m_base, n_base, tid);
    #pragma unroll 1
    for (int t = 0; t < 12; ++t) {
        cpa_wait<0>();                 // stage(t) complete (only outstanding)
        __syncthreads();               // orders compute(t-1) before refill below
        if (t + 1 < 12)                // buffer (t+1)&1: last read by compute(t-1)
            proj_stage(sb, (t + 1) & 1, (t + 1) * 64, m_base, n_base, tid);
        compute(t & 1);                // overlaps stage(t+1) fetch
    }

    #pragma unroll
    for (int g = 0; g < 8; ++g) {
        int c = n_base + warp_n * 64 + 8 * g + 2 * lc;
        float b0 = bo[c], b1 = bo[c + 1];
        #pragma unroll
        for (int f = 0; f < 2; ++f) {
            int r = m_base + warp_m * 32 + 16 * f + lr;
            *(float2*)&y[(size_t)r * CCH + c] =
                make_float2(acc[f][g][0] + b0, acc[f][g][1] + b1);
            *(float2*)&y[(size_t)(r + 8) * CCH + c] =
                make_float2(acc[f][g][2] + b0, acc[f][g][3] + b1);
        }
    }
}

// ============================================================================
extern "C" void kernel_launch(void* const* d_in, const int* in_sizes, int n_in,
                              void* d_out, int out_size)
{
    const float* x  = (const float*)d_in[0];
    const float* Wq = (const float*)d_in[1];
    const float* Wk = (const float*)d_in[2];
    const float* Wv = (const float*)d_in[3];
    const float* Wo = (const float*)d_in[4];
    const float* bo = (const float*)d_in[5];
    float* y = (float*)d_out;

    cudaFuncSetAttribute(attn_kernel, cudaFuncAttributeMaxDynamicSharedMemorySize, SMEMB);
    cudaFuncSetAttribute(proj_kernel, cudaFuncAttributeMaxDynamicSharedMemorySize, PROJ_SMEM);

    split_w_kernel<<<576, 256>>>(Wq, Wk, Wv, Wo);
    attn_kernel<<<NWIN * NHEADS, 128, SMEMB>>>(x);
    proj_kernel<<<784 * 6, 256, PROJ_SMEM>>>(bo, y);
}

// round 17
// speedup vs baseline: 1.2642x; 1.2642x over previous
#include <cuda_runtime.h>
#include <cuda_fp16.h>
#include <stdint.h>
#include <math.h>

#define NHEADS 12
#define DH     64
#define LW     49
#define CCH    768
#define NWIN   2048
#define MROWS  (NWIN * LW)                 // 100352

// ---------------- device-global fp16 planes --------------------------------
__device__ __half g_sh[(size_t)MROWS * CCH];          // attention out
__device__ __half g_wqh[12 * 4096], g_wkh[12 * 4096], g_wvh[12 * 4096];
__device__ __half g_woh[589824];

// ---------------- helpers ---------------------------------------------------
__device__ __forceinline__ void mma_f16(float c[4], const uint32_t a[4],
                                        uint32_t b0, uint32_t b1) {
    asm volatile(
        "mma.sync.aligned.m16n8k16.row.col.f32.f16.f16.f32 "
        "{%0,%1,%2,%3},{%4,%5,%6,%7},{%8,%9},{%0,%1,%2,%3};\n"
        : "+f"(c[0]), "+f"(c[1]), "+f"(c[2]), "+f"(c[3])
        : "r"(a[0]), "r"(a[1]), "r"(a[2]), "r"(a[3]), "r"(b0), "r"(b1));
}

__device__ __forceinline__ void ldsm4(uint32_t r[4], uint32_t saddr) {
    asm volatile("ldmatrix.sync.aligned.m8n8.x4.shared.b16 {%0,%1,%2,%3},[%4];"
                 : "=r"(r[0]), "=r"(r[1]), "=r"(r[2]), "=r"(r[3]) : "r"(saddr));
}

__device__ __forceinline__ void ldsm4t(uint32_t r[4], uint32_t saddr) {
    asm volatile("ldmatrix.sync.aligned.m8n8.x4.trans.shared.b16 {%0,%1,%2,%3},[%4];"
                 : "=r"(r[0]), "=r"(r[1]), "=r"(r[2]), "=r"(r[3]) : "r"(saddr));
}

__device__ __forceinline__ uint32_t packh(__half a, __half b) {
    __half2 t; t.x = a; t.y = b;
    return *reinterpret_cast<uint32_t*>(&t);
}

__device__ __forceinline__ void cpa16(uint32_t dst, const void* src) {
    asm volatile("cp.async.cg.shared.global [%0], [%1], 16;" :: "r"(dst), "l"(src));
}
__device__ __forceinline__ void cpa_commit() { asm volatile("cp.async.commit_group;"); }
template<int N> __device__ __forceinline__ void cpa_wait() {
    asm volatile("cp.async.wait_group %0;" :: "n"(N));
}

// SW128-swizzled byte offset within a plane of 128-B rows.
__device__ __forceinline__ uint32_t swo(int row, uint32_t col) {
    return ((uint32_t)row << 7) + (col ^ (((uint32_t)row & 7u) << 4));
}

// ============================================================================
// Prep: weights, all hi-only fp16.
// ============================================================================
__global__ void split_w_kernel(const float* __restrict__ Wq, const float* __restrict__ Wk,
                               const float* __restrict__ Wv, const float* __restrict__ Wo) {
    int np = 589824 / 2;
    for (int i = blockIdx.x * blockDim.x + threadIdx.x; i < np;
         i += gridDim.x * blockDim.x) {
        float2 v = ((const float2*)Wo)[i];
        ((uint32_t*)g_woh)[i] = packh(__float2half(v.x), __float2half(v.y));
        if (i < 24576) {
            float2 q = ((const float2*)Wq)[i];
            ((uint32_t*)g_wqh)[i] = packh(__float2half(q.x), __float2half(q.y));
            float2 k = ((const float2*)Wk)[i];
            ((uint32_t*)g_wkh)[i] = packh(__float2half(k.x), __float2half(k.y));
            float2 w = ((const float2*)Wv)[i];
            ((uint32_t*)g_wvh)[i] = packh(__float2half(w.x), __float2half(w.y));
        }
    }
}

// ============================================================================
// Kernel A: fused QKV projection + attention, fp16, SW128 unpadded planes.
// Planes (8192 B): 0=x 1=Wq 2=Wk->V 3=Q->P 4=K 5=Wv. Sc aliases planes 0-1.
// Phases: stage (x LDGs first) | QK (cache x frags) | scores+V | softmax | PV.
// ============================================================================
#define PLB   8192
#define SMEMB (6 * PLB)                // 49152 B -> 4 CTAs/SM
#define SCST  65

__device__ __forceinline__ void gemm_pass(float acc[2][4][4], uint32_t aBase,
                                          uint32_t bBase, int mbase, int nbase,
                                          int lane) {
    const int r16 = lane & 15;
    const uint32_t kaq = (lane >> 4) * 16;
    #pragma unroll
    for (int kc = 0; kc < 4; ++kc) {
        uint32_t ka = kaq + kc * 32;
        uint32_t a0[4], a1[4], b0[4], b1[4];
        uint32_t a0a = aBase + swo(mbase + r16, ka);
        uint32_t b0a = bBase + swo(nbase + r16, ka);
        ldsm4(a0, a0a);
        ldsm4(a1, a0a + 2048);
        ldsm4(b0, b0a);
        ldsm4(b1, b0a + 2048);
        mma_f16(acc[0][0], a0, b0[0], b0[2]);
        mma_f16(acc[0][1], a0, b0[1], b0[3]);
        mma_f16(acc[0][2], a0, b1[0], b1[2]);
        mma_f16(acc[0][3], a0, b1[1], b1[3]);
        mma_f16(acc[1][0], a1, b0[0], b0[2]);
        mma_f16(acc[1][1], a1, b0[1], b0[3]);
        mma_f16(acc[1][2], a1, b1[0], b1[2]);
        mma_f16(acc[1][3], a1, b1[1], b1[3]);
    }
}

// A row-major, B row-major [k][n] via ldmatrix.trans (for P @ V)
__device__ __forceinline__ void gemm_pass_tb(float acc[2][4][4], uint32_t aBase,
                                             uint32_t bBase, int mbase, int nbase,
                                             int lane) {
    const int r16 = lane & 15;
    const uint32_t kaq = (lane >> 4) * 16;
    const int krow = ((lane >> 4) << 3) + (lane & 7);
    const int nch = ((lane >> 3) & 1) * 8;
    #pragma unroll
    for (int kc = 0; kc < 4; ++kc) {
        uint32_t ka = kaq + kc * 32;
        uint32_t a0[4], a1[4], b0[4], b1[4];
        uint32_t a0a = aBase + swo(mbase + r16, ka);
        ldsm4(a0, a0a);
        ldsm4(a1, a0a + 2048);
        const int rowB = kc * 16 + krow;
        ldsm4t(b0, bBase + swo(rowB, (nbase + nch) * 2));
        ldsm4t(b1, bBase + swo(rowB, (nbase + 16 + nch) * 2));
        mma_f16(acc[0][0], a0, b0[0], b0[2]);
        mma_f16(acc[0][1], a0, b0[1], b0[3]);
        mma_f16(acc[0][2], a0, b1[0], b1[2]);
        mma_f16(acc[0][3], a0, b1[1], b1[3]);
        mma_f16(acc[1][0], a1, b0[0], b0[2]);
        mma_f16(acc[1][1], a1, b0[1], b0[3]);
        mma_f16(acc[1][2], a1, b1[0], b1[2]);
        mma_f16(acc[1][3], a1, b1[1], b1[3]);
    }
}

__global__ void __launch_bounds__(128, 4)
attn_kernel(const float* __restrict__ x)
{
    extern __shared__ char smc[];
    float* Sc = (float*)smc;               // fp32 scores, aliases planes 0-1

    const int tid = threadIdx.x, lane = tid & 31, wid = tid >> 5;
    const int warp_m = wid >> 1, warp_n = wid & 1;
    const int mbase = warp_m * 32, nbase = warp_n * 32;
    const int lr = lane >> 2, lc = lane & 3;

    const int h = blockIdx.x % NHEADS;
    const int n = blockIdx.x / NHEADS;
    const int b = n >> 6, hb = (n >> 3) & 7, wb = n & 7;

    const uint32_t sb = (uint32_t)__cvta_generic_to_shared(smc);
    const uint32_t sX = sb, sWQ = sb + PLB, sWK = sb + 2 * PLB;
    const uint32_t sV = sb + 2 * PLB;      // V overwrites Wk
    const uint32_t sQ = sb + 3 * PLB;      // Q, later P
    const uint32_t sK = sb + 4 * PLB;
    const uint32_t sWV = sb + 5 * PLB;

    // ---- issue x fp32 LDGs FIRST (latency overlaps cp.async issue below) ----
    float4 xf0[4], xf1[4];
    int xl[4], xch[4];
    #pragma unroll
    for (int it = 0; it < 4; ++it) {
        int q = tid + it * 128;
        int l = q >> 3, ch = q & 7;
        xl[it] = l; xch[it] = ch;
        xf0[it] = make_float4(0.f, 0.f, 0.f, 0.f);
        xf1[it] = make_float4(0.f, 0.f, 0.f, 0.f);
        if (l < LW) {
            int i = l / 7, j = l - i * 7;
            const float* src = x + (((size_t)(b * 56 + hb * 7 + i)) * 56 + (wb * 7 + j)) * CCH
                               + h * DH + ch * 8;
            xf0[it] = *(const float4*)src;
            xf1[it] = *(const float4*)(src + 4);
        }
    }

    // ---- cp.async weights (Wq->1, Wk->2, Wv->5), swizzled ----
    for (int q = tid; q < 1536; q += 128) {
        int pl = q >> 9;
        int rem = q & 511, e = rem >> 3, ch = rem & 7;
        const __half* src = (pl == 0 ? g_wqh : pl == 1 ? g_wkh : g_wvh)
                            + h * 4096 + e * 64 + ch * 8;
        uint32_t plane = (pl == 0) ? 1u : (pl == 1) ? 2u : 5u;
        cpa16(sb + plane * PLB + swo(e, ch * 16), src);
    }
    cpa_commit();

    // ---- convert + store x (LDGs have had time to land) ----
    #pragma unroll
    for (int it = 0; it < 4; ++it) {
        uint4 hv;
        hv.x = packh(__float2half(xf0[it].x), __float2half(xf0[it].y));
        hv.y = packh(__float2half(xf0[it].z), __float2half(xf0[it].w));
        hv.z = packh(__float2half(xf1[it].x), __float2half(xf1[it].y));
        hv.w = packh(__float2half(xf1[it].z), __float2half(xf1[it].w));
        *(uint4*)(smc + swo(xl[it], xch[it] * 16)) = hv;
    }
    cpa_wait<0>();
    __syncthreads();                        // barrier 1

    // ---- merged Q & K projections; CACHE x A-fragments in registers ----
    uint32_t axc[4][2][4];
    {
        float aq[2][4][4] = {}, ak[2][4][4] = {};
        const int r16 = lane & 15;
        const uint32_t kaq = (lane >> 4) * 16;
        #pragma unroll
        for (int kc = 0; kc < 4; ++kc) {
            uint32_t ka = kaq + kc * 32;
            uint32_t bq0[4], bq1[4], bk0[4], bk1[4];
            uint32_t a0a = sX + swo(mbase + r16, ka);
            uint32_t q0a = sWQ + swo(nbase + r16, ka);
            uint32_t k0a = sWK + swo(nbase + r16, ka);
            ldsm4(axc[kc][0], a0a); ldsm4(axc[kc][1], a0a + 2048);
            ldsm4(bq0, q0a); ldsm4(bq1, q0a + 2048);
            ldsm4(bk0, k0a); ldsm4(bk1, k0a + 2048);
            mma_f16(aq[0][0], axc[kc][0], bq0[0], bq0[2]);
            mma_f16(aq[0][1], axc[kc][0], bq0[1], bq0[3]);
            mma_f16(aq[0][2], axc[kc][0], bq1[0], bq1[2]);
            mma_f16(aq[0][3], axc[kc][0], bq1[1], bq1[3]);
            mma_f16(aq[1][0], axc[kc][1], bq0[0], bq0[2]);
            mma_f16(aq[1][1], axc[kc][1], bq0[1], bq0[3]);
            mma_f16(aq[1][2], axc[kc][1], bq1[0], bq1[2]);
            mma_f16(aq[1][3], axc[kc][1], bq1[1], bq1[3]);
            mma_f16(ak[0][0], axc[kc][0], bk0[0], bk0[2]);
            mma_f16(ak[0][1], axc[kc][0], bk0[1], bk0[3]);
            mma_f16(ak[0][2], axc[kc][0], bk1[0], bk1[2]);
            mma_f16(ak[0][3], axc[kc][0], bk1[1], bk1[3]);
            mma_f16(ak[1][0], axc[kc][1], bk0[0], bk0[2]);
            mma_f16(ak[1][1], axc[kc][1], bk0[1], bk0[3]);
            mma_f16(ak[1][2], axc[kc][1], bk1[0], bk1[2]);
            mma_f16(ak[1][3], axc[kc][1], bk1[1], bk1[3]);
        }
        #pragma unroll
        for (int f = 0; f < 2; ++f)
            #pragma unroll
            for (int g = 0; g < 4; ++g) {
                int r = mbase + 16 * f + lr;
                uint32_t off = swo(r, (uint32_t)(nbase + 8 * g + 2 * lc) * 2);
                *(uint32_t*)(smc + 3 * PLB + off) =
                    packh(__float2half(aq[f][g][0]), __float2half(aq[f][g][1]));
                *(uint32_t*)(smc + 3 * PLB + off + 1024) =
                    packh(__float2half(aq[f][g][2]), __float2half(aq[f][g][3]));
                *(uint32_t*)(smc + 4 * PLB + off) =
                    packh(__float2half(ak[f][g][0]), __float2half(ak[f][g][1]));
                *(uint32_t*)(smc + 4 * PLB + off + 1024) =
                    packh(__float2half(ak[f][g][2]), __float2half(ak[f][g][3]));
            }
    }
    __syncthreads();                        // barrier 2 (Wq/Wk dead, x via regs)

    // ---- MERGED phase: scores (Q@K^T -> Sc over x planes) + V (cached x) ----
    {
        // scores; warp_n==1 skips g==3 (cols 56-63, all masked by softmax)
        float acc[2][4][4] = {};
        const int r16 = lane & 15;
        const uint32_t kaq = (lane >> 4) * 16;
        const int gmax = (warp_n == 0) ? 4 : 3;
        #pragma unroll
        for (int kc = 0; kc < 4; ++kc) {
            uint32_t ka = kaq + kc * 32;
            uint32_t a0[4], a1[4], b0[4], b1[4];
            uint32_t a0a = sQ + swo(mbase + r16, ka);
            uint32_t b0a = sK + swo(nbase + r16, ka);
            ldsm4(a0, a0a); ldsm4(a1, a0a + 2048);
            ldsm4(b0, b0a); ldsm4(b1, b0a + 2048);
            mma_f16(acc[0][0], a0, b0[0], b0[2]);
            mma_f16(acc[0][1], a0, b0[1], b0[3]);
            mma_f16(acc[0][2], a0, b1[0], b1[2]);
            mma_f16(acc[1][0], a1, b0[0], b0[2]);
            mma_f16(acc[1][1], a1, b0[1], b0[3]);
            mma_f16(acc[1][2], a1, b1[0], b1[2]);
            if (gmax == 4) {
                mma_f16(acc[0][3], a0, b1[1], b1[3]);
                mma_f16(acc[1][3], a1, b1[1], b1[3]);
            }
        }
        #pragma unroll
        for (int f = 0; f < 2; ++f)
            for (int g = 0; g < 4; ++g) {
                if (g >= gmax) break;
                int r = mbase + 16 * f + lr;
                int c = nbase + 8 * g + 2 * lc;
                if (r < LW) {
                    Sc[r * SCST + c]     = acc[f][g][0] * 0.125f;
                    Sc[r * SCST + c + 1] = acc[f][g][1] * 0.125f;
                }
                if (r + 8 < LW) {
                    Sc[(r + 8) * SCST + c]     = acc[f][g][2] * 0.125f;
                    Sc[(r + 8) * SCST + c + 1] = acc[f][g][3] * 0.125f;
                }
            }
    }
    {
        // V = x @ Wv using cached A-fragments (no x plane reads)
        float acc[2][4][4] = {};
        const int r16 = lane & 15;
        const uint32_t kaq = (lane >> 4) * 16;
        #pragma unroll
        for (int kc = 0; kc < 4; ++kc) {
            uint32_t ka = kaq + kc * 32;
            uint32_t b0[4], b1[4];
            uint32_t b0a = sWV + swo(nbase + r16, ka);
            ldsm4(b0, b0a);
            ldsm4(b1, b0a + 2048);
            mma_f16(acc[0][0], axc[kc][0], b0[0], b0[2]);
            mma_f16(acc[0][1], axc[kc][0], b0[1], b0[3]);
            mma_f16(acc[0][2], axc[kc][0], b1[0], b1[2]);
            mma_f16(acc[0][3], axc[kc][0], b1[1], b1[3]);
            mma_f16(acc[1][0], axc[kc][1], b0[0], b0[2]);
            mma_f16(acc[1][1], axc[kc][1], b0[1], b0[3]);
            mma_f16(acc[1][2], axc[kc][1], b1[0], b1[2]);
            mma_f16(acc[1][3], axc[kc][1], b1[1], b1[3]);
        }
        #pragma unroll
        for (int f = 0; f < 2; ++f)
            #pragma unroll
            for (int g = 0; g < 4; ++g) {
                int r = mbase + 16 * f + lr;
                uint32_t off = swo(r, (uint32_t)(nbase + 8 * g + 2 * lc) * 2);
                *(uint32_t*)(smc + 2 * PLB + off) =
                    packh(__float2half(acc[f][g][0]), __float2half(acc[f][g][1]));
                *(uint32_t*)(smc + 2 * PLB + off + 1024) =
                    packh(__float2half(acc[f][g][2]), __float2half(acc[f][g][3]));
            }
    }
    __syncthreads();                        // barrier 3

    // ---- softmax: 2 threads per row, write P into plane 3 (over Q) ----
    if (tid < 2 * LW) {
        const int r = tid >> 1, half = tid & 1;
        const unsigned msk = (tid < 96) ? 0xFFFFFFFFu : 0x3u;
        float* row = Sc + r * SCST;
        const int m0 = half ? 25 : 0, m1 = half ? LW : 25;
        float mx = -1e30f;
        #pragma unroll
        for (int m = m0; m < m1; ++m) mx = fmaxf(mx, row[m]);
        mx = fmaxf(mx, __shfl_xor_sync(msk, mx, 1));
        float s = 0.f;
        #pragma unroll
        for (int m = m0; m < m1; ++m) { float e = __expf(row[m] - mx); row[m] = e; s += e; }
        s += __shfl_xor_sync(msk, s, 1);
        float inv = 1.f / s;
        __syncwarp(msk);
        #pragma unroll
        for (int mw = half * 16; mw < half * 16 + 16; ++mw) {
            int mc = 2 * mw;
            float p0 = (mc     < LW) ? row[mc] * inv     : 0.f;
            float p1 = (mc + 1 < LW) ? row[mc + 1] * inv : 0.f;
            *(uint32_t*)(smc + 3 * PLB + swo(r, (uint32_t)mw * 4)) =
                packh(__float2half(p0), __float2half(p1));
        }
    }
    __syncthreads();                        // barrier 4

    // ---- out = P @ V (trans-B ldsm), store fp16 to g_sh ----
    {
        float acc[2][4][4] = {};
        gemm_pass_tb(acc, sQ, sV, mbase, nbase, lane);
        #pragma unroll
        for (int f = 0; f < 2; ++f)
            #pragma unroll
            for (int g = 0; g < 4; ++g) {
                int r = mbase + 16 * f + lr;
                int c = nbase + 8 * g + 2 * lc;
                if (r < LW) {
                    size_t off = ((size_t)n * LW + r) * CCH + h * DH + c;
                    *(uint32_t*)(g_sh + off) =
                        packh(__float2half(acc[f][g][0]), __float2half(acc[f][g][1]));
                }
                if (r + 8 < LW) {
                    size_t off = ((size_t)n * LW + r + 8) * CCH + h * DH + c;
                    *(uint32_t*)(g_sh + off) =
                        packh(__float2half(acc[f][g][2]), __float2half(acc[f][g][3]));
                }
            }
    }
}

// ============================================================================
// Kernel B: y = S @ Wo^T + bo, pure fp16 GEMM. CTA tile 128x128, warp 32x64,
// BK=64, SW128 rows, 3-stage cp.async pipeline, 256 threads, 2 CTAs/SM.
// (round-14 configuration — measured optimum)
// ============================================================================
#define PSTG 32768
#define QA   0
#define QB   16384
#define PROJ_SMEM (3 * PSTG)

__device__ __forceinline__ void proj_stage(uint32_t sb, int s, int kt,
                                           int m_base, int n_base, int tid) {
    const uint32_t base = sb + s * PSTG;
    #pragma unroll
    for (int c = tid; c < 1024; c += 256) {
        int row = c >> 3, ch = c & 7;
        cpa16(base + QA + swo(row, ch * 16),
              g_sh + (size_t)(m_base + row) * CCH + kt + ch * 8);
    }
    #pragma unroll
    for (int c = tid; c < 1024; c += 256) {
        int row = c >> 3, ch = c & 7;
        cpa16(base + QB + swo(row, ch * 16),
              g_woh + (size_t)(n_base + row) * CCH + kt + ch * 8);
    }
    cpa_commit();
}

__global__ void __launch_bounds__(256, 2)
proj_kernel(const float* __restrict__ bo, float* __restrict__ y)
{
    extern __shared__ char psm[];
    const int tid = threadIdx.x, lane = tid & 31, wid = tid >> 5;
    const int warp_m = wid >> 1, warp_n = wid & 1;
    const int lr = lane >> 2, lc = lane & 3;
    const int n_base = (blockIdx.x % 6) * 128;
    const int m_base = (blockIdx.x / 6) * 128;
    const uint32_t sb = (uint32_t)__cvta_generic_to_shared(psm);
    const int r16 = lane & 15;
    const uint32_t kaq = (lane >> 4) * 16;

    float acc[2][8][4] = {};

    auto compute = [&](int s) {
        const uint32_t aB = sb + s * PSTG + QA;
        const uint32_t bB = sb + s * PSTG + QB;
        #pragma unroll
        for (int kc = 0; kc < 4; ++kc) {
            uint32_t ka = kaq + kc * 32;
            uint32_t a0[4], a1[4], bf[4][4];
            uint32_t a0a = aB + swo(warp_m * 32 + r16, ka);
            ldsm4(a0, a0a);
            ldsm4(a1, a0a + 2048);
            #pragma unroll
            for (int nn = 0; nn < 4; ++nn)
                ldsm4(bf[nn], bB + swo(warp_n * 64 + nn * 16 + r16, ka));
            #pragma unroll
            for (int nn = 0; nn < 4; ++nn) {
                mma_f16(acc[0][2 * nn],     a0, bf[nn][0], bf[nn][2]);
                mma_f16(acc[0][2 * nn + 1], a0, bf[nn][1], bf[nn][3]);
                mma_f16(acc[1][2 * nn],     a1, bf[nn][0], bf[nn][2]);
                mma_f16(acc[1][2 * nn + 1], a1, bf[nn][1], bf[nn][3]);
            }
        }
    };

    proj_stage(sb, 0, 0, m_base, n_base, tid);
    proj_stage(sb, 1, 64, m_base, n_base, tid);
    #pragma unroll 1
    for (int t = 0; t < 12; ++t) {
        if (t < 11) cpa_wait<1>(); else cpa_wait<0>();
        __syncthreads();
        compute(t % 3);
        if (t + 2 < 12) proj_stage(sb, (t + 2) % 3, (t + 2) * 64, m_base, n_base, tid);
    }

    #pragma unroll
    for (int g = 0; g < 8; ++g) {
        int c = n_base + warp_n * 64 + 8 * g + 2 * lc;
        float b0 = bo[c], b1 = bo[c + 1];
        #pragma unroll
        for (int f = 0; f < 2; ++f) {
            int r = m_base + warp_m * 32 + 16 * f + lr;
            *(float2*)&y[(size_t)r * CCH + c] =
                make_float2(acc[f][g][0] + b0, acc[f][g][1] + b1);
            *(float2*)&y[(size_t)(r + 8) * CCH + c] =
                make_float2(acc[f][g][2] + b0, acc[f][g][3] + b1);
        }
    }
}

// ============================================================================
extern "C" void kernel_launch(void* const* d_in, const int* in_sizes, int n_in,
                              void* d_out, int out_size)
{
    const float* x  = (const float*)d_in[0];
    const float* Wq = (const float*)d_in[1];
    const float* Wk = (const float*)d_in[2];
    const float* Wv = (const float*)d_in[3];
    const float* Wo = (const float*)d_in[4];
    const float* bo = (const float*)d_in[5];
    float* y = (float*)d_out;

    cudaFuncSetAttribute(attn_kernel, cudaFuncAttributeMaxDynamicSharedMemorySize, SMEMB);
    cudaFuncSetAttribute(proj_kernel, cudaFuncAttributeMaxDynamicSharedMemorySize, PROJ_SMEM);

    split_w_kernel<<<576, 256>>>(Wq, Wk, Wv, Wo);
    attn_kernel<<<NWIN * NHEADS, 128, SMEMB>>>(x);
    proj_kernel<<<784 * 6, 256, PROJ_SMEM>>>(bo, y);
}